// round 5
// baseline (speedup 1.0000x reference)
#include <cuda_runtime.h>
#include <cuda_fp16.h>
#include <cstdint>

#define NN 150000
#define NE 2400000

// Scratch (static __device__ — no allocations allowed)
__device__ float   g_xs[NN * 8];      // x * dinv, padded 6->8 (4.8 MB)
__device__ float   g_agg1[NN * 8];    // pass-1 accumulator     (4.8 MB)
__device__ __half2 g_hs16[NN * 16];   // (h@W2)*dinv as fp16    (9.6 MB)
__device__ float   g_agg2[NN * 32];   // pass-2 accumulator     (19.2 MB)
__device__ float   g_dinv[NN];        // deg -> dinv

// ---------------------------------------------------------------------------
__global__ void k_deg_init(int n) {
    int i = blockIdx.x * blockDim.x + threadIdx.x;
    if (i < n) g_dinv[i] = 1.0f;
}

__global__ void k_deg_edges(const int* __restrict__ dst, int ne) {
    int e = blockIdx.x * blockDim.x + threadIdx.x;
    if (e < ne) {
        float* p = &g_dinv[__ldg(&dst[e])];
        asm volatile("red.global.add.f32 [%0], %1;" :: "l"(p), "f"(1.0f) : "memory");
    }
}

// prep: dinv = rsqrt(deg); xs = x*dinv (pad 8); agg1 = xs (self-loop init)
__global__ void k_prep(const float* __restrict__ x, int n) {
    int i = blockIdx.x * blockDim.x + threadIdx.x;
    if (i >= n) return;
    float dinv = rsqrtf(g_dinv[i]);
    g_dinv[i] = dinv;
    const float2* x2 = (const float2*)x;
    float2 a0 = __ldg(&x2[i * 3 + 0]);
    float2 a1 = __ldg(&x2[i * 3 + 1]);
    float2 a2 = __ldg(&x2[i * 3 + 2]);
    float4 v0 = make_float4(a0.x * dinv, a0.y * dinv, a1.x * dinv, a1.y * dinv);
    float4 v1 = make_float4(a2.x * dinv, a2.y * dinv, 0.f, 0.f);
    float4* xs4 = (float4*)g_xs;
    float4* ag4 = (float4*)g_agg1;
    xs4[i * 2 + 0] = v0; xs4[i * 2 + 1] = v1;
    ag4[i * 2 + 0] = v0; ag4[i * 2 + 1] = v1;
}

// pass-1 edge scatter: agg1[dst] += xs[src], two edges per thread (fp32)
__global__ void k_scat1(const int* __restrict__ src, const int* __restrict__ dst, int ne) {
    int t = blockIdx.x * blockDim.x + threadIdx.x;
    int half = (ne + 1) >> 1;
    if (t >= half) return;
    int e0 = t, e1 = t + half;
    bool has1 = (e1 < ne);

    int s0 = __ldg(&src[e0]);
    int d0 = __ldg(&dst[e0]);
    int s1 = has1 ? __ldg(&src[e1]) : 0;
    int d1 = has1 ? __ldg(&dst[e1]) : 0;

    const float4* xs4 = (const float4*)g_xs;
    float4 a0 = __ldg(&xs4[(long)s0 * 2 + 0]);
    float4 a1 = __ldg(&xs4[(long)s0 * 2 + 1]);
    float4 b0, b1;
    if (has1) {
        b0 = __ldg(&xs4[(long)s1 * 2 + 0]);
        b1 = __ldg(&xs4[(long)s1 * 2 + 1]);
    }

    float4* p0 = (float4*)&g_agg1[(long)d0 * 8];
    asm volatile("red.global.add.v4.f32 [%0], {%1, %2, %3, %4};"
                 :: "l"(p0), "f"(a0.x), "f"(a0.y), "f"(a0.z), "f"(a0.w) : "memory");
    asm volatile("red.global.add.v2.f32 [%0], {%1, %2};"
                 :: "l"(p0 + 1), "f"(a1.x), "f"(a1.y) : "memory");
    if (has1) {
        float4* p1 = (float4*)&g_agg1[(long)d1 * 8];
        asm volatile("red.global.add.v4.f32 [%0], {%1, %2, %3, %4};"
                     :: "l"(p1), "f"(b0.x), "f"(b0.y), "f"(b0.z), "f"(b0.w) : "memory");
        asm volatile("red.global.add.v2.f32 [%0], {%1, %2};"
                     :: "l"(p1 + 1), "f"(b1.x), "f"(b1.y) : "memory");
    }
}

// node: aggx = dinv*agg1; h = relu(aggx@W1+b1); hw = h@W2;
//       hs16 = fp16(hw*dinv); agg2 init = fp32 hw*dinv (self-loop, full precision)
__global__ void k_node(const float* __restrict__ W1, const float* __restrict__ b1,
                       const float* __restrict__ W2, int n) {
    __shared__ float sW1[6 * 32];
    __shared__ float sb1[32];
    __shared__ float sW2[32 * 32];
    for (int t = threadIdx.x; t < 192; t += blockDim.x) sW1[t] = W1[t];
    for (int t = threadIdx.x; t < 1024; t += blockDim.x) sW2[t] = W2[t];
    if (threadIdx.x < 32) sb1[threadIdx.x] = b1[threadIdx.x];
    __syncthreads();
    int i = blockIdx.x * blockDim.x + threadIdx.x;
    if (i >= n) return;

    float dinv = g_dinv[i];
    float a[6];
#pragma unroll
    for (int k = 0; k < 6; k++) a[k] = g_agg1[i * 8 + k] * dinv;

    float h[32];
#pragma unroll
    for (int j = 0; j < 32; j++) {
        float s = sb1[j];
#pragma unroll
        for (int k = 0; k < 6; k++) s += a[k] * sW1[k * 32 + j];
        h[j] = fmaxf(s, 0.f);
    }
    float acc[32];
#pragma unroll
    for (int j = 0; j < 32; j++) acc[j] = 0.f;
#pragma unroll
    for (int k = 0; k < 32; k++) {
        float hk = h[k];
#pragma unroll
        for (int j = 0; j < 32; j++) acc[j] += hk * sW2[k * 32 + j];
    }
    float4* ag4 = (float4*)&g_agg2[(long)i * 32];
    __half2 hbuf[16];
#pragma unroll
    for (int q = 0; q < 8; q++) {
        float4 v = make_float4(acc[4*q] * dinv, acc[4*q+1] * dinv,
                               acc[4*q+2] * dinv, acc[4*q+3] * dinv);
        ag4[q] = v;
        hbuf[2*q + 0] = __float22half2_rn(make_float2(v.x, v.y));
        hbuf[2*q + 1] = __float22half2_rn(make_float2(v.z, v.w));
    }
    uint4* o16 = (uint4*)&g_hs16[(long)i * 16];
    const uint4* hb = (const uint4*)hbuf;
#pragma unroll
    for (int q = 0; q < 4; q++) o16[q] = hb[q];
}

// pass-2 edge scatter: agg2[dst] += fp32(hs16[src]); 4 threads/edge, 2 edges/thread
__global__ void k_scat2(const int* __restrict__ src, const int* __restrict__ dst,
                        int ne, int half) {
    long tid = (long)blockIdx.x * blockDim.x + threadIdx.x;
    long e0 = tid >> 2;
    int  c = (int)(tid & 3);
    if (e0 >= half) return;
    long e1 = e0 + half;
    bool has1 = (e1 < ne);

    int s0 = __ldg(&src[e0]);
    int d0 = __ldg(&dst[e0]);
    int s1 = has1 ? __ldg(&src[e1]) : 0;
    int d1 = has1 ? __ldg(&dst[e1]) : 0;

    const uint4* hs = (const uint4*)g_hs16;
    uint4 u0 = __ldg(&hs[(long)s0 * 4 + c]);
    uint4 u1;
    if (has1) u1 = __ldg(&hs[(long)s1 * 4 + c]);

    {
        float2 f0 = __half22float2(*(const __half2*)&u0.x);
        float2 f1 = __half22float2(*(const __half2*)&u0.y);
        float2 f2 = __half22float2(*(const __half2*)&u0.z);
        float2 f3 = __half22float2(*(const __half2*)&u0.w);
        float4* p = (float4*)&g_agg2[(long)d0 * 32] + 2 * c;
        asm volatile("red.global.add.v4.f32 [%0], {%1, %2, %3, %4};"
                     :: "l"(p), "f"(f0.x), "f"(f0.y), "f"(f1.x), "f"(f1.y) : "memory");
        asm volatile("red.global.add.v4.f32 [%0], {%1, %2, %3, %4};"
                     :: "l"(p + 1), "f"(f2.x), "f"(f2.y), "f"(f3.x), "f"(f3.y) : "memory");
    }
    if (has1) {
        float2 f0 = __half22float2(*(const __half2*)&u1.x);
        float2 f1 = __half22float2(*(const __half2*)&u1.y);
        float2 f2 = __half22float2(*(const __half2*)&u1.z);
        float2 f3 = __half22float2(*(const __half2*)&u1.w);
        float4* p = (float4*)&g_agg2[(long)d1 * 32] + 2 * c;
        asm volatile("red.global.add.v4.f32 [%0], {%1, %2, %3, %4};"
                     :: "l"(p), "f"(f0.x), "f"(f0.y), "f"(f1.x), "f"(f1.y) : "memory");
        asm volatile("red.global.add.v4.f32 [%0], {%1, %2, %3, %4};"
                     :: "l"(p + 1), "f"(f2.x), "f"(f2.y), "f"(f3.x), "f"(f3.y) : "memory");
    }
}

// heads: features = dinv*agg2 + b2 -> out; two tiny MLPs
__global__ void k_heads(const float* __restrict__ b2,
                        const float* __restrict__ Wt1, const float* __restrict__ bt1,
                        const float* __restrict__ Wt2, const float* __restrict__ bt2,
                        const float* __restrict__ Wa1, const float* __restrict__ ba1,
                        const float* __restrict__ Wa2, const float* __restrict__ ba2,
                        float* __restrict__ out, int n) {
    __shared__ float s_b2[32];
    __shared__ float s_Wt1[32 * 16];
    __shared__ float s_bt1[16];
    __shared__ float s_Wt2[16];
    __shared__ float s_Wa1[32 * 16];
    __shared__ float s_ba1[16];
    __shared__ float s_Wa2[16 * 6];
    __shared__ float s_ba2[6];
    __shared__ float s_bt2;
    for (int t = threadIdx.x; t < 512; t += blockDim.x) { s_Wt1[t] = Wt1[t]; s_Wa1[t] = Wa1[t]; }
    for (int t = threadIdx.x; t < 96;  t += blockDim.x) s_Wa2[t] = Wa2[t];
    if (threadIdx.x < 32) s_b2[threadIdx.x] = b2[threadIdx.x];
    if (threadIdx.x < 16) { s_bt1[threadIdx.x] = bt1[threadIdx.x];
                            s_Wt2[threadIdx.x] = Wt2[threadIdx.x];
                            s_ba1[threadIdx.x] = ba1[threadIdx.x]; }
    if (threadIdx.x < 6)  s_ba2[threadIdx.x] = ba2[threadIdx.x];
    if (threadIdx.x == 0) s_bt2 = bt2[0];
    __syncthreads();

    int i = blockIdx.x * blockDim.x + threadIdx.x;
    if (i >= n) return;

    float dinv = g_dinv[i];
    float f[32];
    const float4* ag4 = (const float4*)&g_agg2[(long)i * 32];
#pragma unroll
    for (int q = 0; q < 8; q++) {
        float4 v = ag4[q];
        f[4*q+0] = v.x * dinv + s_b2[4*q+0];
        f[4*q+1] = v.y * dinv + s_b2[4*q+1];
        f[4*q+2] = v.z * dinv + s_b2[4*q+2];
        f[4*q+3] = v.w * dinv + s_b2[4*q+3];
    }

    float4* fout = (float4*)(out + (long)7 * n + (long)i * 32);
#pragma unroll
    for (int q = 0; q < 8; q++)
        fout[q] = make_float4(f[4*q], f[4*q+1], f[4*q+2], f[4*q+3]);

    float t1[16];
#pragma unroll
    for (int j = 0; j < 16; j++) {
        float s = s_bt1[j];
#pragma unroll
        for (int k = 0; k < 32; k++) s += f[k] * s_Wt1[k * 16 + j];
        t1[j] = fmaxf(s, 0.f);
    }
    float topo = s_bt2;
#pragma unroll
    for (int j = 0; j < 16; j++) topo += t1[j] * s_Wt2[j];
    out[i] = topo;

    float a1[16];
#pragma unroll
    for (int j = 0; j < 16; j++) {
        float s = s_ba1[j];
#pragma unroll
        for (int k = 0; k < 32; k++) s += f[k] * s_Wa1[k * 16 + j];
        a1[j] = fmaxf(s, 0.f);
    }
    float attr[6];
#pragma unroll
    for (int m = 0; m < 6; m++) {
        float s = s_ba2[m];
#pragma unroll
        for (int j = 0; j < 16; j++) s += a1[j] * s_Wa2[j * 6 + m];
        attr[m] = s;
    }
    long nb = n;
    out[nb     + (long)i * 3 + 0] = attr[0];
    out[nb     + (long)i * 3 + 1] = attr[1];
    out[nb     + (long)i * 3 + 2] = attr[2];
    out[nb * 4 + (long)i * 3 + 0] = attr[3];
    out[nb * 4 + (long)i * 3 + 1] = attr[4];
    out[nb * 4 + (long)i * 3 + 2] = attr[5];
}

// ---------------------------------------------------------------------------
extern "C" void kernel_launch(void* const* d_in, const int* in_sizes, int n_in,
                              void* d_out, int out_size) {
    const float* x   = (const float*)d_in[0];
    const int*   ei  = (const int*)d_in[1];
    const float* W1  = (const float*)d_in[2];
    const float* b1  = (const float*)d_in[3];
    const float* W2  = (const float*)d_in[4];
    const float* b2  = (const float*)d_in[5];
    const float* Wt1 = (const float*)d_in[6];
    const float* bt1 = (const float*)d_in[7];
    const float* Wt2 = (const float*)d_in[8];
    const float* bt2 = (const float*)d_in[9];
    const float* Wa1 = (const float*)d_in[10];
    const float* ba1 = (const float*)d_in[11];
    const float* Wa2 = (const float*)d_in[12];
    const float* ba2 = (const float*)d_in[13];
    float* out = (float*)d_out;

    int n  = in_sizes[0] / 6;
    int ne = in_sizes[1] / 2;
    const int* src = ei;
    const int* dst = ei + ne;

    const int B = 256;
    int gn = (n + B - 1) / B;
    int ge = (ne + B - 1) / B;
    int half = (ne + 1) >> 1;
    int gs1 = (half + B - 1) / B;
    long s2 = (long)half * 4;
    int gs2 = (int)((s2 + B - 1) / B);

    k_deg_init <<<gn, B>>>(n);
    k_deg_edges<<<ge, B>>>(dst, ne);
    k_prep     <<<gn, B>>>(x, n);
    k_scat1    <<<gs1, B>>>(src, dst, ne);
    k_node     <<<gn, B>>>(W1, b1, W2, n);
    k_scat2    <<<gs2, B>>>(src, dst, ne, half);
    k_heads    <<<gn, B>>>(b2, Wt1, bt1, Wt2, bt2, Wa1, ba1, Wa2, ba2, out, n);
}

// round 6
// speedup vs baseline: 1.1587x; 1.1587x over previous
#include <cuda_runtime.h>
#include <cuda_fp16.h>
#include <cstdint>

#define NN 150000
#define NE 2400000

// Scratch (static __device__ — no allocations allowed)
__device__ float   g_xs[NN * 8];      // x * dinv, padded 6->8 (4.8 MB)
__device__ float   g_agg1[NN * 8];    // pass-1 accumulator     (4.8 MB)
__device__ __half2 g_hs16[NN * 16];   // (h@W2)*dinv as fp16    (9.6 MB)
__device__ float   g_agg2[NN * 32];   // pass-2 accumulator     (19.2 MB)
__device__ float   g_dinv[NN];        // deg -> dinv

// ---------------------------------------------------------------------------
__global__ void k_deg_init(int n) {
    int i = blockIdx.x * blockDim.x + threadIdx.x;
    if (i < n) g_dinv[i] = 1.0f;
}

__global__ void k_deg_edges(const int* __restrict__ dst, int ne) {
    int e = blockIdx.x * blockDim.x + threadIdx.x;
    if (e < ne) {
        float* p = &g_dinv[__ldg(&dst[e])];
        asm volatile("red.global.add.f32 [%0], %1;" :: "l"(p), "f"(1.0f) : "memory");
    }
}

// prep: dinv = rsqrt(deg); xs = x*dinv (pad 8); agg1 = xs (self-loop init)
__global__ void k_prep(const float* __restrict__ x, int n) {
    int i = blockIdx.x * blockDim.x + threadIdx.x;
    if (i >= n) return;
    float dinv = rsqrtf(g_dinv[i]);
    g_dinv[i] = dinv;
    const float2* x2 = (const float2*)x;
    float2 a0 = __ldg(&x2[i * 3 + 0]);
    float2 a1 = __ldg(&x2[i * 3 + 1]);
    float2 a2 = __ldg(&x2[i * 3 + 2]);
    float4 v0 = make_float4(a0.x * dinv, a0.y * dinv, a1.x * dinv, a1.y * dinv);
    float4 v1 = make_float4(a2.x * dinv, a2.y * dinv, 0.f, 0.f);
    float4* xs4 = (float4*)g_xs;
    float4* ag4 = (float4*)g_agg1;
    xs4[i * 2 + 0] = v0; xs4[i * 2 + 1] = v1;
    ag4[i * 2 + 0] = v0; ag4[i * 2 + 1] = v1;
}

// pass-1 edge scatter: agg1[dst] += xs[src], two edges per thread (fp32)
__global__ void k_scat1(const int* __restrict__ src, const int* __restrict__ dst, int ne) {
    int t = blockIdx.x * blockDim.x + threadIdx.x;
    int half = (ne + 1) >> 1;
    if (t >= half) return;
    int e0 = t, e1 = t + half;
    bool has1 = (e1 < ne);

    int s0 = __ldg(&src[e0]);
    int d0 = __ldg(&dst[e0]);
    int s1 = has1 ? __ldg(&src[e1]) : 0;
    int d1 = has1 ? __ldg(&dst[e1]) : 0;

    const float4* xs4 = (const float4*)g_xs;
    float4 a0 = __ldg(&xs4[(long)s0 * 2 + 0]);
    float4 a1 = __ldg(&xs4[(long)s0 * 2 + 1]);
    float4 b0, b1;
    if (has1) {
        b0 = __ldg(&xs4[(long)s1 * 2 + 0]);
        b1 = __ldg(&xs4[(long)s1 * 2 + 1]);
    }

    float4* p0 = (float4*)&g_agg1[(long)d0 * 8];
    asm volatile("red.global.add.v4.f32 [%0], {%1, %2, %3, %4};"
                 :: "l"(p0), "f"(a0.x), "f"(a0.y), "f"(a0.z), "f"(a0.w) : "memory");
    asm volatile("red.global.add.v2.f32 [%0], {%1, %2};"
                 :: "l"(p0 + 1), "f"(a1.x), "f"(a1.y) : "memory");
    if (has1) {
        float4* p1 = (float4*)&g_agg1[(long)d1 * 8];
        asm volatile("red.global.add.v4.f32 [%0], {%1, %2, %3, %4};"
                     :: "l"(p1), "f"(b0.x), "f"(b0.y), "f"(b0.z), "f"(b0.w) : "memory");
        asm volatile("red.global.add.v2.f32 [%0], {%1, %2};"
                     :: "l"(p1 + 1), "f"(b1.x), "f"(b1.y) : "memory");
    }
}

// node: aggx = dinv*agg1; h = relu(aggx@W1+b1); hw = h@W2;
//       hs16 = fp16(hw*dinv); agg2 init = fp32 hw*dinv (self-loop, full precision)
__global__ void k_node(const float* __restrict__ W1, const float* __restrict__ b1,
                       const float* __restrict__ W2, int n) {
    __shared__ float sW1[6 * 32];
    __shared__ float sb1[32];
    __shared__ float sW2[32 * 32];
    for (int t = threadIdx.x; t < 192; t += blockDim.x) sW1[t] = W1[t];
    for (int t = threadIdx.x; t < 1024; t += blockDim.x) sW2[t] = W2[t];
    if (threadIdx.x < 32) sb1[threadIdx.x] = b1[threadIdx.x];
    __syncthreads();
    int i = blockIdx.x * blockDim.x + threadIdx.x;
    if (i >= n) return;

    float dinv = g_dinv[i];
    float a[6];
#pragma unroll
    for (int k = 0; k < 6; k++) a[k] = g_agg1[i * 8 + k] * dinv;

    float h[32];
#pragma unroll
    for (int j = 0; j < 32; j++) {
        float s = sb1[j];
#pragma unroll
        for (int k = 0; k < 6; k++) s += a[k] * sW1[k * 32 + j];
        h[j] = fmaxf(s, 0.f);
    }
    float acc[32];
#pragma unroll
    for (int j = 0; j < 32; j++) acc[j] = 0.f;
#pragma unroll
    for (int k = 0; k < 32; k++) {
        float hk = h[k];
#pragma unroll
        for (int j = 0; j < 32; j++) acc[j] += hk * sW2[k * 32 + j];
    }
    float4* ag4 = (float4*)&g_agg2[(long)i * 32];
    __half2 hbuf[16];
#pragma unroll
    for (int q = 0; q < 8; q++) {
        float4 v = make_float4(acc[4*q] * dinv, acc[4*q+1] * dinv,
                               acc[4*q+2] * dinv, acc[4*q+3] * dinv);
        ag4[q] = v;
        hbuf[2*q + 0] = __float22half2_rn(make_float2(v.x, v.y));
        hbuf[2*q + 1] = __float22half2_rn(make_float2(v.z, v.w));
    }
    uint4* o16 = (uint4*)&g_hs16[(long)i * 16];
    const uint4* hb = (const uint4*)hbuf;
#pragma unroll
    for (int q = 0; q < 4; q++) o16[q] = hb[q];
}

// pass-2 edge scatter: agg2[dst] += fp32(hs16[src])
// EXACT round-4 mapping: 8 threads/edge, 2 edges/thread, 1 red.v4 per edge-slot.
// Only the gather shrinks: uint2 (8B fp16) instead of float4 (16B fp32).
__global__ void k_scat2(const int* __restrict__ src, const int* __restrict__ dst,
                        int ne, int half) {
    long tid = (long)blockIdx.x * blockDim.x + threadIdx.x;
    long e0 = tid >> 3;
    int  c = (int)(tid & 7);
    if (e0 >= half) return;
    long e1 = e0 + half;
    bool has1 = (e1 < ne);

    int s0 = __ldg(&src[e0]);
    int d0 = __ldg(&dst[e0]);
    int s1 = has1 ? __ldg(&src[e1]) : 0;
    int d1 = has1 ? __ldg(&dst[e1]) : 0;

    const uint2* hs = (const uint2*)g_hs16;   // 8 x uint2 per row
    uint2 u0 = __ldg(&hs[(long)s0 * 8 + c]);
    uint2 u1;
    if (has1) u1 = __ldg(&hs[(long)s1 * 8 + c]);

    {
        float2 f0 = __half22float2(*(const __half2*)&u0.x);
        float2 f1 = __half22float2(*(const __half2*)&u0.y);
        float4* p = (float4*)&g_agg2[(long)d0 * 32] + c;
        asm volatile("red.global.add.v4.f32 [%0], {%1, %2, %3, %4};"
                     :: "l"(p), "f"(f0.x), "f"(f0.y), "f"(f1.x), "f"(f1.y) : "memory");
    }
    if (has1) {
        float2 f0 = __half22float2(*(const __half2*)&u1.x);
        float2 f1 = __half22float2(*(const __half2*)&u1.y);
        float4* p = (float4*)&g_agg2[(long)d1 * 32] + c;
        asm volatile("red.global.add.v4.f32 [%0], {%1, %2, %3, %4};"
                     :: "l"(p), "f"(f0.x), "f"(f0.y), "f"(f1.x), "f"(f1.y) : "memory");
    }
}

// heads: features = dinv*agg2 + b2 -> out; two tiny MLPs
__global__ void k_heads(const float* __restrict__ b2,
                        const float* __restrict__ Wt1, const float* __restrict__ bt1,
                        const float* __restrict__ Wt2, const float* __restrict__ bt2,
                        const float* __restrict__ Wa1, const float* __restrict__ ba1,
                        const float* __restrict__ Wa2, const float* __restrict__ ba2,
                        float* __restrict__ out, int n) {
    __shared__ float s_b2[32];
    __shared__ float s_Wt1[32 * 16];
    __shared__ float s_bt1[16];
    __shared__ float s_Wt2[16];
    __shared__ float s_Wa1[32 * 16];
    __shared__ float s_ba1[16];
    __shared__ float s_Wa2[16 * 6];
    __shared__ float s_ba2[6];
    __shared__ float s_bt2;
    for (int t = threadIdx.x; t < 512; t += blockDim.x) { s_Wt1[t] = Wt1[t]; s_Wa1[t] = Wa1[t]; }
    for (int t = threadIdx.x; t < 96;  t += blockDim.x) s_Wa2[t] = Wa2[t];
    if (threadIdx.x < 32) s_b2[threadIdx.x] = b2[threadIdx.x];
    if (threadIdx.x < 16) { s_bt1[threadIdx.x] = bt1[threadIdx.x];
                            s_Wt2[threadIdx.x] = Wt2[threadIdx.x];
                            s_ba1[threadIdx.x] = ba1[threadIdx.x]; }
    if (threadIdx.x < 6)  s_ba2[threadIdx.x] = ba2[threadIdx.x];
    if (threadIdx.x == 0) s_bt2 = bt2[0];
    __syncthreads();

    int i = blockIdx.x * blockDim.x + threadIdx.x;
    if (i >= n) return;

    float dinv = g_dinv[i];
    float f[32];
    const float4* ag4 = (const float4*)&g_agg2[(long)i * 32];
#pragma unroll
    for (int q = 0; q < 8; q++) {
        float4 v = ag4[q];
        f[4*q+0] = v.x * dinv + s_b2[4*q+0];
        f[4*q+1] = v.y * dinv + s_b2[4*q+1];
        f[4*q+2] = v.z * dinv + s_b2[4*q+2];
        f[4*q+3] = v.w * dinv + s_b2[4*q+3];
    }

    float4* fout = (float4*)(out + (long)7 * n + (long)i * 32);
#pragma unroll
    for (int q = 0; q < 8; q++)
        fout[q] = make_float4(f[4*q], f[4*q+1], f[4*q+2], f[4*q+3]);

    float t1[16];
#pragma unroll
    for (int j = 0; j < 16; j++) {
        float s = s_bt1[j];
#pragma unroll
        for (int k = 0; k < 32; k++) s += f[k] * s_Wt1[k * 16 + j];
        t1[j] = fmaxf(s, 0.f);
    }
    float topo = s_bt2;
#pragma unroll
    for (int j = 0; j < 16; j++) topo += t1[j] * s_Wt2[j];
    out[i] = topo;

    float a1[16];
#pragma unroll
    for (int j = 0; j < 16; j++) {
        float s = s_ba1[j];
#pragma unroll
        for (int k = 0; k < 32; k++) s += f[k] * s_Wa1[k * 16 + j];
        a1[j] = fmaxf(s, 0.f);
    }
    float attr[6];
#pragma unroll
    for (int m = 0; m < 6; m++) {
        float s = s_ba2[m];
#pragma unroll
        for (int j = 0; j < 16; j++) s += a1[j] * s_Wa2[j * 6 + m];
        attr[m] = s;
    }
    long nb = n;
    out[nb     + (long)i * 3 + 0] = attr[0];
    out[nb     + (long)i * 3 + 1] = attr[1];
    out[nb     + (long)i * 3 + 2] = attr[2];
    out[nb * 4 + (long)i * 3 + 0] = attr[3];
    out[nb * 4 + (long)i * 3 + 1] = attr[4];
    out[nb * 4 + (long)i * 3 + 2] = attr[5];
}

// ---------------------------------------------------------------------------
extern "C" void kernel_launch(void* const* d_in, const int* in_sizes, int n_in,
                              void* d_out, int out_size) {
    const float* x   = (const float*)d_in[0];
    const int*   ei  = (const int*)d_in[1];
    const float* W1  = (const float*)d_in[2];
    const float* b1  = (const float*)d_in[3];
    const float* W2  = (const float*)d_in[4];
    const float* b2  = (const float*)d_in[5];
    const float* Wt1 = (const float*)d_in[6];
    const float* bt1 = (const float*)d_in[7];
    const float* Wt2 = (const float*)d_in[8];
    const float* bt2 = (const float*)d_in[9];
    const float* Wa1 = (const float*)d_in[10];
    const float* ba1 = (const float*)d_in[11];
    const float* Wa2 = (const float*)d_in[12];
    const float* ba2 = (const float*)d_in[13];
    float* out = (float*)d_out;

    int n  = in_sizes[0] / 6;
    int ne = in_sizes[1] / 2;
    const int* src = ei;
    const int* dst = ei + ne;

    const int B = 256;
    int gn = (n + B - 1) / B;
    int ge = (ne + B - 1) / B;
    int half = (ne + 1) >> 1;
    int gs1 = (half + B - 1) / B;
    long s2 = (long)half * 8;
    int gs2 = (int)((s2 + B - 1) / B);

    k_deg_init <<<gn, B>>>(n);
    k_deg_edges<<<ge, B>>>(dst, ne);
    k_prep     <<<gn, B>>>(x, n);
    k_scat1    <<<gs1, B>>>(src, dst, ne);
    k_node     <<<gn, B>>>(W1, b1, W2, n);
    k_scat2    <<<gs2, B>>>(src, dst, ne, half);
    k_heads    <<<gn, B>>>(b2, Wt1, bt1, Wt2, bt2, Wa1, ba1, Wa2, ba2, out, n);
}

// round 7
// speedup vs baseline: 1.2028x; 1.0380x over previous
#include <cuda_runtime.h>
#include <cuda_fp16.h>

#define NN 150000
#define NE 2400000

// Scratch (static __device__ — no allocations allowed)
__device__ int     g_cnt[NN];         // per-dst edge counts
__device__ int     g_off[NN + 1];     // CSR offsets (by dst)
__device__ int     g_cur[NN];         // fill cursors
__device__ int     g_csr[NE];         // src grouped by dst
__device__ int     g_part[256];       // scan partials
__device__ float   g_dinv[NN];
__device__ float   g_xs[NN * 8];      // x*dinv padded 6->8 (4.8 MB)
__device__ __half2 g_hs16[NN * 16];   // (h@W2)*dinv fp16   (9.6 MB)

// ---------------------------------------------------------------------------
__global__ void k_zero(int n) {
    int i = blockIdx.x * blockDim.x + threadIdx.x;
    if (i < n) g_cnt[i] = 0;
}

__global__ void k_hist(const int* __restrict__ dst, int ne) {
    int e = blockIdx.x * blockDim.x + threadIdx.x;
    if (e < ne) atomicAdd(&g_cnt[__ldg(&dst[e])], 1);
}

// block-local exclusive scan of g_cnt -> g_off, block sums -> g_part
__global__ void k_scan1(int n) {
    __shared__ int sh[1024];
    int i = blockIdx.x * 1024 + threadIdx.x;
    int v = (i < n) ? g_cnt[i] : 0;
    sh[threadIdx.x] = v;
    __syncthreads();
#pragma unroll
    for (int o = 1; o < 1024; o <<= 1) {
        int t = 0;
        if ((int)threadIdx.x >= o) t = sh[threadIdx.x - o];
        __syncthreads();
        if ((int)threadIdx.x >= o) sh[threadIdx.x] += t;
        __syncthreads();
    }
    if (i < n) g_off[i] = sh[threadIdx.x] - v;
    if (threadIdx.x == 1023) g_part[blockIdx.x] = sh[1023];
}

// exclusive scan of partials (single block; nb <= 256)
__global__ void k_scan2(int nb) {
    __shared__ int sh[256];
    int v = ((int)threadIdx.x < nb) ? g_part[threadIdx.x] : 0;
    sh[threadIdx.x] = v;
    __syncthreads();
#pragma unroll
    for (int o = 1; o < 256; o <<= 1) {
        int t = 0;
        if ((int)threadIdx.x >= o) t = sh[threadIdx.x - o];
        __syncthreads();
        if ((int)threadIdx.x >= o) sh[threadIdx.x] += t;
        __syncthreads();
    }
    if ((int)threadIdx.x < nb) g_part[threadIdx.x] = sh[threadIdx.x] - v;
}

// finish: global offsets, cursors, dinv, xs = x*dinv (padded 8)
__global__ void k_finish(const float* __restrict__ x, int n, int ne) {
    int i = blockIdx.x * blockDim.x + threadIdx.x;
    if (i >= n) return;
    int off = g_off[i] + g_part[i >> 10];
    g_off[i] = off;
    g_cur[i] = off;
    float dinv = rsqrtf((float)g_cnt[i] + 1.0f);
    g_dinv[i] = dinv;
    const float2* x2 = (const float2*)x;
    float2 a0 = __ldg(&x2[i * 3 + 0]);
    float2 a1 = __ldg(&x2[i * 3 + 1]);
    float2 a2 = __ldg(&x2[i * 3 + 2]);
    float4* xs4 = (float4*)g_xs;
    xs4[i * 2 + 0] = make_float4(a0.x * dinv, a0.y * dinv, a1.x * dinv, a1.y * dinv);
    xs4[i * 2 + 1] = make_float4(a2.x * dinv, a2.y * dinv, 0.f, 0.f);
    if (i == 0) g_off[n] = ne;
}

__global__ void k_fill(const int* __restrict__ src, const int* __restrict__ dst, int ne) {
    int e = blockIdx.x * blockDim.x + threadIdx.x;
    if (e >= ne) return;
    int d = __ldg(&dst[e]);
    int pos = atomicAdd(&g_cur[d], 1);
    g_csr[pos] = __ldg(&src[e]);
}

// ---------------------------------------------------------------------------
// conv1 fused: gather xs over CSR (+self) -> aggx; h=relu(aggx@W1+b1);
// hw=h@W2; write hs16 = fp16(hw*dinv). Thread per node, register accumulation.
__global__ void k_conv1(const float* __restrict__ W1, const float* __restrict__ b1,
                        const float* __restrict__ W2, int n) {
    __shared__ float sW1[6 * 32];
    __shared__ float sb1[32];
    __shared__ float sW2[32 * 32];
    for (int t = threadIdx.x; t < 192; t += blockDim.x) sW1[t] = W1[t];
    for (int t = threadIdx.x; t < 1024; t += blockDim.x) sW2[t] = W2[t];
    if (threadIdx.x < 32) sb1[threadIdx.x] = b1[threadIdx.x];
    __syncthreads();
    int i = blockIdx.x * blockDim.x + threadIdx.x;
    if (i >= n) return;

    float dinv = g_dinv[i];
    const float4* xs4 = (const float4*)g_xs;
    float4 xa = xs4[(long)i * 2 + 0];
    float4 xb = xs4[(long)i * 2 + 1];
    float c0 = xa.x, c1 = xa.y, c2 = xa.z, c3 = xa.w, c4 = xb.x, c5 = xb.y;

    int b = g_off[i], e = g_off[i + 1];
    int j = b;
    for (; j + 1 < e; j += 2) {
        int s0 = __ldg(&g_csr[j]);
        int s1 = __ldg(&g_csr[j + 1]);
        float4 p0 = __ldg(&xs4[(long)s0 * 2 + 0]);
        float4 p1 = __ldg(&xs4[(long)s0 * 2 + 1]);
        float4 q0 = __ldg(&xs4[(long)s1 * 2 + 0]);
        float4 q1 = __ldg(&xs4[(long)s1 * 2 + 1]);
        c0 += p0.x; c1 += p0.y; c2 += p0.z; c3 += p0.w; c4 += p1.x; c5 += p1.y;
        c0 += q0.x; c1 += q0.y; c2 += q0.z; c3 += q0.w; c4 += q1.x; c5 += q1.y;
    }
    if (j < e) {
        int s0 = __ldg(&g_csr[j]);
        float4 p0 = __ldg(&xs4[(long)s0 * 2 + 0]);
        float4 p1 = __ldg(&xs4[(long)s0 * 2 + 1]);
        c0 += p0.x; c1 += p0.y; c2 += p0.z; c3 += p0.w; c4 += p1.x; c5 += p1.y;
    }
    float a[6] = {c0 * dinv, c1 * dinv, c2 * dinv, c3 * dinv, c4 * dinv, c5 * dinv};

    float h[32];
#pragma unroll
    for (int jj = 0; jj < 32; jj++) {
        float s = sb1[jj];
#pragma unroll
        for (int k = 0; k < 6; k++) s += a[k] * sW1[k * 32 + jj];
        h[jj] = fmaxf(s, 0.f);
    }
    float acc[32];
#pragma unroll
    for (int jj = 0; jj < 32; jj++) acc[jj] = 0.f;
#pragma unroll
    for (int k = 0; k < 32; k++) {
        float hk = h[k];
#pragma unroll
        for (int jj = 0; jj < 32; jj++) acc[jj] += hk * sW2[k * 32 + jj];
    }
    __half2 hbuf[16];
#pragma unroll
    for (int q = 0; q < 16; q++)
        hbuf[q] = __float22half2_rn(make_float2(acc[2*q] * dinv, acc[2*q+1] * dinv));
    uint4* o16 = (uint4*)&g_hs16[(long)i * 16];
    const uint4* hb = (const uint4*)hbuf;
#pragma unroll
    for (int q = 0; q < 4; q++) o16[q] = hb[q];
}

// ---------------------------------------------------------------------------
// dequant-accumulate one uint4 (8 fp16) into f[0..7]
__device__ __forceinline__ void acc8(float* f, const uint4& u) {
    float2 t0 = __half22float2(*(const __half2*)&u.x);
    float2 t1 = __half22float2(*(const __half2*)&u.y);
    float2 t2 = __half22float2(*(const __half2*)&u.z);
    float2 t3 = __half22float2(*(const __half2*)&u.w);
    f[0] += t0.x; f[1] += t0.y; f[2] += t1.x; f[3] += t1.y;
    f[4] += t2.x; f[5] += t2.y; f[6] += t3.x; f[7] += t3.y;
}

// feat fused: gather hs16 over CSR (+self) -> f = dinv*sum + b2; write features;
// fused MLP heads. Thread per node.
__global__ void k_feat(const float* __restrict__ b2,
                       const float* __restrict__ Wt1, const float* __restrict__ bt1,
                       const float* __restrict__ Wt2, const float* __restrict__ bt2,
                       const float* __restrict__ Wa1, const float* __restrict__ ba1,
                       const float* __restrict__ Wa2, const float* __restrict__ ba2,
                       float* __restrict__ out, int n) {
    __shared__ float s_b2[32];
    __shared__ float s_Wt1[32 * 16];
    __shared__ float s_bt1[16];
    __shared__ float s_Wt2[16];
    __shared__ float s_Wa1[32 * 16];
    __shared__ float s_ba1[16];
    __shared__ float s_Wa2[16 * 6];
    __shared__ float s_ba2[6];
    __shared__ float s_bt2;
    for (int t = threadIdx.x; t < 512; t += blockDim.x) { s_Wt1[t] = Wt1[t]; s_Wa1[t] = Wa1[t]; }
    for (int t = threadIdx.x; t < 96;  t += blockDim.x) s_Wa2[t] = Wa2[t];
    if (threadIdx.x < 32) s_b2[threadIdx.x] = b2[threadIdx.x];
    if (threadIdx.x < 16) { s_bt1[threadIdx.x] = bt1[threadIdx.x];
                            s_Wt2[threadIdx.x] = Wt2[threadIdx.x];
                            s_ba1[threadIdx.x] = ba1[threadIdx.x]; }
    if (threadIdx.x < 6)  s_ba2[threadIdx.x] = ba2[threadIdx.x];
    if (threadIdx.x == 0) s_bt2 = bt2[0];
    __syncthreads();

    int i = blockIdx.x * blockDim.x + threadIdx.x;
    if (i >= n) return;

    float dinv = g_dinv[i];
    const uint4* hs = (const uint4*)g_hs16;   // 4 x uint4 per row

    float f[32];
    {   // init from own row (self-loop term, shares the dinv_d factor)
        uint4 u0 = __ldg(&hs[(long)i * 4 + 0]);
        uint4 u1 = __ldg(&hs[(long)i * 4 + 1]);
        uint4 u2 = __ldg(&hs[(long)i * 4 + 2]);
        uint4 u3 = __ldg(&hs[(long)i * 4 + 3]);
#pragma unroll
        for (int q = 0; q < 32; q++) f[q] = 0.f;
        acc8(f + 0, u0); acc8(f + 8, u1); acc8(f + 16, u2); acc8(f + 24, u3);
    }

    int b = g_off[i], e = g_off[i + 1];
    int j = b;
    for (; j + 1 < e; j += 2) {
        int s0 = __ldg(&g_csr[j]);
        int s1 = __ldg(&g_csr[j + 1]);
        uint4 a0 = __ldg(&hs[(long)s0 * 4 + 0]);
        uint4 a1 = __ldg(&hs[(long)s0 * 4 + 1]);
        uint4 a2 = __ldg(&hs[(long)s0 * 4 + 2]);
        uint4 a3 = __ldg(&hs[(long)s0 * 4 + 3]);
        uint4 b0 = __ldg(&hs[(long)s1 * 4 + 0]);
        uint4 b1 = __ldg(&hs[(long)s1 * 4 + 1]);
        uint4 b2v = __ldg(&hs[(long)s1 * 4 + 2]);
        uint4 b3 = __ldg(&hs[(long)s1 * 4 + 3]);
        acc8(f + 0, a0); acc8(f + 8, a1); acc8(f + 16, a2); acc8(f + 24, a3);
        acc8(f + 0, b0); acc8(f + 8, b1); acc8(f + 16, b2v); acc8(f + 24, b3);
    }
    if (j < e) {
        int s0 = __ldg(&g_csr[j]);
        uint4 a0 = __ldg(&hs[(long)s0 * 4 + 0]);
        uint4 a1 = __ldg(&hs[(long)s0 * 4 + 1]);
        uint4 a2 = __ldg(&hs[(long)s0 * 4 + 2]);
        uint4 a3 = __ldg(&hs[(long)s0 * 4 + 3]);
        acc8(f + 0, a0); acc8(f + 8, a1); acc8(f + 16, a2); acc8(f + 24, a3);
    }
#pragma unroll
    for (int q = 0; q < 32; q++) f[q] = f[q] * dinv + s_b2[q];

    // features at offset 7*n
    float4* fout = (float4*)(out + (long)7 * n + (long)i * 32);
#pragma unroll
    for (int q = 0; q < 8; q++)
        fout[q] = make_float4(f[4*q], f[4*q+1], f[4*q+2], f[4*q+3]);

    float t1[16];
#pragma unroll
    for (int jj = 0; jj < 16; jj++) {
        float s = s_bt1[jj];
#pragma unroll
        for (int k = 0; k < 32; k++) s += f[k] * s_Wt1[k * 16 + jj];
        t1[jj] = fmaxf(s, 0.f);
    }
    float topo = s_bt2;
#pragma unroll
    for (int jj = 0; jj < 16; jj++) topo += t1[jj] * s_Wt2[jj];
    out[i] = topo;

    float a1h[16];
#pragma unroll
    for (int jj = 0; jj < 16; jj++) {
        float s = s_ba1[jj];
#pragma unroll
        for (int k = 0; k < 32; k++) s += f[k] * s_Wa1[k * 16 + jj];
        a1h[jj] = fmaxf(s, 0.f);
    }
    float attr[6];
#pragma unroll
    for (int m = 0; m < 6; m++) {
        float s = s_ba2[m];
#pragma unroll
        for (int jj = 0; jj < 16; jj++) s += a1h[jj] * s_Wa2[jj * 6 + m];
        attr[m] = s;
    }
    long nb = n;
    out[nb     + (long)i * 3 + 0] = attr[0];
    out[nb     + (long)i * 3 + 1] = attr[1];
    out[nb     + (long)i * 3 + 2] = attr[2];
    out[nb * 4 + (long)i * 3 + 0] = attr[3];
    out[nb * 4 + (long)i * 3 + 1] = attr[4];
    out[nb * 4 + (long)i * 3 + 2] = attr[5];
}

// ---------------------------------------------------------------------------
extern "C" void kernel_launch(void* const* d_in, const int* in_sizes, int n_in,
                              void* d_out, int out_size) {
    const float* x   = (const float*)d_in[0];
    const int*   ei  = (const int*)d_in[1];
    const float* W1  = (const float*)d_in[2];
    const float* b1  = (const float*)d_in[3];
    const float* W2  = (const float*)d_in[4];
    const float* b2  = (const float*)d_in[5];
    const float* Wt1 = (const float*)d_in[6];
    const float* bt1 = (const float*)d_in[7];
    const float* Wt2 = (const float*)d_in[8];
    const float* bt2 = (const float*)d_in[9];
    const float* Wa1 = (const float*)d_in[10];
    const float* ba1 = (const float*)d_in[11];
    const float* Wa2 = (const float*)d_in[12];
    const float* ba2 = (const float*)d_in[13];
    float* out = (float*)d_out;

    int n  = in_sizes[0] / 6;
    int ne = in_sizes[1] / 2;
    const int* src = ei;
    const int* dst = ei + ne;

    const int B = 256;
    int gn = (n + B - 1) / B;
    int ge = (ne + B - 1) / B;
    int nsb = (n + 1023) / 1024;

    k_zero  <<<gn, B>>>(n);
    k_hist  <<<ge, B>>>(dst, ne);
    k_scan1 <<<nsb, 1024>>>(n);
    k_scan2 <<<1, 256>>>(nsb);
    k_finish<<<gn, B>>>(x, n, ne);
    k_fill  <<<ge, B>>>(src, dst, ne);
    k_conv1 <<<gn, B>>>(W1, b1, W2, n);
    k_feat  <<<gn, B>>>(b2, Wt1, bt1, Wt2, bt2, Wa1, ba1, Wa2, ba2, out, n);
}